// round 2
// baseline (speedup 1.0000x reference)
#include <cuda_runtime.h>
#include <cstdint>

// softmax(Q K^T) V, unscaled. B=4,H=16,S=2048,D=64 fp32.
// Flash style. Lane pairs split D (32 dims/thread), shfl combines dots.
// cp.async double-buffered K/V tiles. Packed f32x2 FMA throughout.

#define BHEADS 64
#define SEQ    2048
#define HD     64
#define HHD    (HD / 2)          // 32 dims per thread
#define BT     128               // threads per block
#define ROWS   (BT / 2)          // 64 query rows per block
#define BN     32                // keys per tile
#define NTILES (SEQ / BN)
#define TILE_F (BN * HD)         // 2048 floats per tile

typedef unsigned long long u64;

__device__ __forceinline__ u64 fma2(u64 a, u64 b, u64 c) {
    u64 d; asm("fma.rn.f32x2 %0, %1, %2, %3;" : "=l"(d) : "l"(a), "l"(b), "l"(c)); return d;
}
__device__ __forceinline__ u64 mul2(u64 a, u64 b) {
    u64 d; asm("mul.rn.f32x2 %0, %1, %2;" : "=l"(d) : "l"(a), "l"(b)); return d;
}
__device__ __forceinline__ u64 pack2(float lo, float hi) {
    u64 d; asm("mov.b64 %0, {%1, %2};" : "=l"(d) : "f"(lo), "f"(hi)); return d;
}
__device__ __forceinline__ float hsum2(u64 a) {
    float lo, hi; asm("mov.b64 {%0, %1}, %2;" : "=f"(lo), "=f"(hi) : "l"(a)); return lo + hi;
}
__device__ __forceinline__ void cpasync16(uint32_t saddr, const void* g) {
    asm volatile("cp.async.cg.shared.global [%0], [%1], 16;" :: "r"(saddr), "l"(g));
}
__device__ __forceinline__ void cpcommit() {
    asm volatile("cp.async.commit_group;");
}

__global__ __launch_bounds__(BT, 4)
void attn_flash_split(const float* __restrict__ Q,
                      const float* __restrict__ K,
                      const float* __restrict__ V,
                      float* __restrict__ O) {
    __shared__ __align__(16) float sK[2][TILE_F];
    __shared__ __align__(16) float sV[2][TILE_F];

    const int tid  = threadIdx.x;
    const int half = tid & 1;                 // which 32 dims this thread owns
    const int rloc = tid >> 1;                // local query row 0..63
    const int head = blockIdx.y;
    const int row  = blockIdx.x * ROWS + rloc;

    const size_t head_base = (size_t)head * SEQ * HD;
    const float* kbase = K + head_base;
    const float* vbase = V + head_base;

    // q slice: 32 floats = 16 f32x2
    u64 q2[HHD / 2];
    {
        const u64* qp = (const u64*)(Q + head_base + (size_t)row * HD + half * HHD);
        #pragma unroll
        for (int i = 0; i < HHD / 2; ++i) q2[i] = qp[i];
    }
    u64 o2[HHD / 2];
    #pragma unroll
    for (int i = 0; i < HHD / 2; ++i) o2[i] = 0ull;

    float m = -1e30f, l = 0.0f;

    const uint32_t skb = (uint32_t)__cvta_generic_to_shared(&sK[0][0]);
    const uint32_t svb = (uint32_t)__cvta_generic_to_shared(&sV[0][0]);

    // stage tile 0 into buffer 0
    {
        const float* kg = kbase;
        const float* vg = vbase;
        #pragma unroll
        for (int i = 0; i < TILE_F / 4 / BT; ++i) {       // 4 chunks each for K and V
            int idx = tid + i * BT;                       // 16B chunk index
            cpasync16(skb + idx * 16, kg + idx * 4);
            cpasync16(svb + idx * 16, vg + idx * 4);
        }
        cpcommit();
    }

    for (int t = 0; t < NTILES; ++t) {
        __syncthreads();            // everyone done with the buffer we're about to refill
        const int cur = t & 1;
        if (t + 1 < NTILES) {
            const int nxt = (t + 1) & 1;
            const float* kg = kbase + (size_t)(t + 1) * TILE_F;
            const float* vg = vbase + (size_t)(t + 1) * TILE_F;
            const uint32_t skn = skb + nxt * TILE_F * 4;
            const uint32_t svn = svb + nxt * TILE_F * 4;
            #pragma unroll
            for (int i = 0; i < TILE_F / 4 / BT; ++i) {
                int idx = tid + i * BT;
                cpasync16(skn + idx * 16, kg + idx * 4);
                cpasync16(svn + idx * 16, vg + idx * 4);
            }
            cpcommit();
            asm volatile("cp.async.wait_group 1;");
        } else {
            asm volatile("cp.async.wait_group 0;");
        }
        __syncthreads();            // tile t visible to all

        const float* sk = &sK[cur][0];
        const float* sv = &sV[cur][0];

        // ---- scores: partial dot over this thread's 32 dims, combine across pair
        float s[BN];
        #pragma unroll
        for (int j = 0; j < BN; ++j) {
            const ulonglong2* krow = (const ulonglong2*)(sk + j * HD + half * HHD);
            u64 aa = 0ull, ab = 0ull;
            #pragma unroll
            for (int i = 0; i < HHD / 4; ++i) {
                ulonglong2 kk = krow[i];                  // LDS.128
                aa = fma2(q2[2 * i + 0], kk.x, aa);
                ab = fma2(q2[2 * i + 1], kk.y, ab);
            }
            float part = hsum2(aa) + hsum2(ab);
            s[j] = part + __shfl_xor_sync(0xffffffffu, part, 1);
        }

        // ---- online softmax
        float tmax = s[0];
        #pragma unroll
        for (int j = 1; j < BN; ++j) tmax = fmaxf(tmax, s[j]);
        float mnew = fmaxf(m, tmax);
        float corr = __expf(m - mnew);
        l *= corr;
        u64 c2 = pack2(corr, corr);
        #pragma unroll
        for (int i = 0; i < HHD / 2; ++i) o2[i] = mul2(o2[i], c2);

        // ---- P·V over this thread's 32 dims
        #pragma unroll
        for (int j = 0; j < BN; ++j) {
            float p = __expf(s[j] - mnew);
            l += p;
            u64 p2 = pack2(p, p);
            const ulonglong2* vrow = (const ulonglong2*)(sv + j * HD + half * HHD);
            #pragma unroll
            for (int i = 0; i < HHD / 4; ++i) {
                ulonglong2 vv = vrow[i];                  // LDS.128
                o2[2 * i + 0] = fma2(p2, vv.x, o2[2 * i + 0]);
                o2[2 * i + 1] = fma2(p2, vv.y, o2[2 * i + 1]);
            }
        }
        m = mnew;
    }

    float inv = 1.0f / l;
    u64 inv2 = pack2(inv, inv);
    u64* op = (u64*)(O + head_base + (size_t)row * HD + half * HHD);
    #pragma unroll
    for (int i = 0; i < HHD / 2; ++i) op[i] = mul2(o2[i], inv2);
}

extern "C" void kernel_launch(void* const* d_in, const int* in_sizes, int n_in,
                              void* d_out, int out_size) {
    const float* Q = (const float*)d_in[0];
    const float* K = (const float*)d_in[1];
    const float* V = (const float*)d_in[2];
    float* O = (float*)d_out;

    dim3 grid(SEQ / ROWS, BHEADS);
    dim3 block(BT);
    attn_flash_split<<<grid, block>>>(Q, K, V, O);
}

// round 6
// speedup vs baseline: 8.7498x; 8.7498x over previous
#include <cuda_runtime.h>
#include <cuda_fp16.h>
#include <cstdint>

// softmax(Q K^T) V  — B=4,H=16,S=2048,D=64 fp32.
// FA2-style mma.sync.m16n8k16 fp16 kernel (portable HMMA; tcgen05 unavailable
// at the harness's compute_103 target). QK^T uses a 3-pass fp16 hi/lo split
// for fp32-grade score accuracy; PV single-pass fp16.

#define SEQ 2048
#define HD  64
#define BM  128          // q-rows per CTA
#define BN  64           // keys per tile
#define NT  (SEQ / BN)
#define BT  256          // 8 warps, 16 q-rows each

#define SM_KH 0          // K hi tile: 64 rows * 128B
#define SM_KL 8192       // K lo tile
#define SM_V  16384      // V tile

// 16B-chunk swizzle within a 128B row (8 chunks): conflict-free ldmatrix.
__device__ __forceinline__ uint32_t swz(uint32_t r, uint32_t c) {
    return r * 128u + ((c ^ (r & 7u)) << 4);
}

__device__ __forceinline__ void ldsm_x4(uint32_t& r0, uint32_t& r1, uint32_t& r2, uint32_t& r3, uint32_t a) {
    asm volatile("ldmatrix.sync.aligned.m8n8.x4.shared.b16 {%0,%1,%2,%3}, [%4];"
                 : "=r"(r0), "=r"(r1), "=r"(r2), "=r"(r3) : "r"(a));
}
__device__ __forceinline__ void ldsm_x2(uint32_t& r0, uint32_t& r1, uint32_t a) {
    asm volatile("ldmatrix.sync.aligned.m8n8.x2.shared.b16 {%0,%1}, [%2];"
                 : "=r"(r0), "=r"(r1) : "r"(a));
}
__device__ __forceinline__ void ldsm_x2t(uint32_t& r0, uint32_t& r1, uint32_t a) {
    asm volatile("ldmatrix.sync.aligned.m8n8.x2.trans.shared.b16 {%0,%1}, [%2];"
                 : "=r"(r0), "=r"(r1) : "r"(a));
}
__device__ __forceinline__ void mma16816(float* d, const uint32_t* a, uint32_t b0, uint32_t b1) {
    asm volatile("mma.sync.aligned.m16n8k16.row.col.f32.f16.f16.f32 "
                 "{%0,%1,%2,%3}, {%4,%5,%6,%7}, {%8,%9}, {%0,%1,%2,%3};"
                 : "+f"(d[0]), "+f"(d[1]), "+f"(d[2]), "+f"(d[3])
                 : "r"(a[0]), "r"(a[1]), "r"(a[2]), "r"(a[3]), "r"(b0), "r"(b1));
}
// pack two f32 -> f16x2 reg {hi, lo}
__device__ __forceinline__ uint32_t packh2(float hi, float lo) {
    uint32_t d;
    asm("cvt.rn.f16x2.f32 %0, %1, %2;" : "=r"(d) : "f"(hi), "f"(lo));
    return d;
}

__global__ __launch_bounds__(BT, 1)
void attn_mma(const float* __restrict__ Q, const float* __restrict__ K,
              const float* __restrict__ V, float* __restrict__ Out) {
    __shared__ __align__(1024) char sm[24576];
    const uint32_t smb = (uint32_t)__cvta_generic_to_shared(sm);

    const int tid  = threadIdx.x;
    const int lane = tid & 31;
    const int wid  = tid >> 5;
    const int lr8  = lane & 7;
    const int hi8  = (lane >> 3) & 1;
    const int g    = lane >> 2;     // c-frag row group
    const int tq   = lane & 3;      // c-frag col pair
    const size_t hb = (size_t)blockIdx.y * SEQ * HD;
    const int qbase = blockIdx.x * BM;
    const int wrow  = wid * 16;

    // ================= Q fragments (hi/lo) via smem staging =================
    uint32_t qh[4][4], ql[4][4];
    {
        float qv[32];
        const float4* qg = (const float4*)(Q + hb + (size_t)qbase * HD);
        #pragma unroll
        for (int i = 0; i < 8; ++i) {
            float4 f = qg[tid + i * BT];
            qv[i*4+0] = f.x; qv[i*4+1] = f.y; qv[i*4+2] = f.z; qv[i*4+3] = f.w;
        }
        // hi pass
        #pragma unroll
        for (int i = 0; i < 8; ++i) {
            int idx = tid + i * BT;
            int r = idx >> 4, c4 = idx & 15;
            uint32_t off = swz(r, c4 >> 1) + (c4 & 1) * 8;
            *(__half2*)(sm + off)     = __halves2half2(__float2half_rn(qv[i*4+0]), __float2half_rn(qv[i*4+1]));
            *(__half2*)(sm + off + 4) = __halves2half2(__float2half_rn(qv[i*4+2]), __float2half_rn(qv[i*4+3]));
        }
        __syncthreads();
        #pragma unroll
        for (int ks = 0; ks < 4; ++ks) {
            int qd = lane >> 3;
            int r = wrow + ((qd & 1) << 3) + lr8;
            int c = ks * 2 + (qd >> 1);
            ldsm_x4(qh[ks][0], qh[ks][1], qh[ks][2], qh[ks][3], smb + swz(r, c));
        }
        __syncthreads();
        // lo pass (residual)
        #pragma unroll
        for (int i = 0; i < 8; ++i) {
            int idx = tid + i * BT;
            int r = idx >> 4, c4 = idx & 15;
            uint32_t off = swz(r, c4 >> 1) + (c4 & 1) * 8;
            float r0 = qv[i*4+0] - __half2float(__float2half_rn(qv[i*4+0]));
            float r1 = qv[i*4+1] - __half2float(__float2half_rn(qv[i*4+1]));
            float r2 = qv[i*4+2] - __half2float(__float2half_rn(qv[i*4+2]));
            float r3 = qv[i*4+3] - __half2float(__float2half_rn(qv[i*4+3]));
            *(__half2*)(sm + off)     = __halves2half2(__float2half_rn(r0), __float2half_rn(r1));
            *(__half2*)(sm + off + 4) = __halves2half2(__float2half_rn(r2), __float2half_rn(r3));
        }
        __syncthreads();
        #pragma unroll
        for (int ks = 0; ks < 4; ++ks) {
            int qd = lane >> 3;
            int r = wrow + ((qd & 1) << 3) + lr8;
            int c = ks * 2 + (qd >> 1);
            ldsm_x4(ql[ks][0], ql[ks][1], ql[ks][2], ql[ks][3], smb + swz(r, c));
        }
        __syncthreads();
    }

    // ================= main loop over key tiles =================
    const float4* kg = (const float4*)(K + hb);
    const float4* vg = (const float4*)(V + hb);
    float4 gk[4], gv[4];
    #pragma unroll
    for (int i = 0; i < 4; ++i) { gk[i] = kg[tid + i * BT]; gv[i] = vg[tid + i * BT]; }

    float O[8][4];
    #pragma unroll
    for (int nd = 0; nd < 8; ++nd)
        #pragma unroll
        for (int j = 0; j < 4; ++j) O[nd][j] = 0.0f;
    float m0 = -1e30f, m1 = -1e30f, l0 = 0.0f, l1 = 0.0f;

    for (int t = 0; t < NT; ++t) {
        // ---- convert + store tile t (from prefetch regs) into smem
        #pragma unroll
        for (int i = 0; i < 4; ++i) {
            int idx = tid + i * BT;
            int r = idx >> 4, c4 = idx & 15;
            uint32_t off = swz(r, c4 >> 1) + (c4 & 1) * 8;
            float fx0 = gk[i].x, fx1 = gk[i].y, fx2 = gk[i].z, fx3 = gk[i].w;
            __half h0 = __float2half_rn(fx0), h1 = __float2half_rn(fx1);
            __half h2 = __float2half_rn(fx2), h3 = __float2half_rn(fx3);
            *(__half2*)(sm + SM_KH + off)     = __halves2half2(h0, h1);
            *(__half2*)(sm + SM_KH + off + 4) = __halves2half2(h2, h3);
            *(__half2*)(sm + SM_KL + off)     = __halves2half2(
                __float2half_rn(fx0 - __half2float(h0)), __float2half_rn(fx1 - __half2float(h1)));
            *(__half2*)(sm + SM_KL + off + 4) = __halves2half2(
                __float2half_rn(fx2 - __half2float(h2)), __float2half_rn(fx3 - __half2float(h3)));
            *(__half2*)(sm + SM_V + off)      = __halves2half2(__float2half_rn(gv[i].x), __float2half_rn(gv[i].y));
            *(__half2*)(sm + SM_V + off + 4)  = __halves2half2(__float2half_rn(gv[i].z), __float2half_rn(gv[i].w));
        }
        __syncthreads();

        // ---- prefetch tile t+1 (completes during compute below)
        if (t + 1 < NT) {
            const float4* kg2 = kg + (size_t)(t + 1) * (BN * HD / 4);
            const float4* vg2 = vg + (size_t)(t + 1) * (BN * HD / 4);
            #pragma unroll
            for (int i = 0; i < 4; ++i) { gk[i] = kg2[tid + i * BT]; gv[i] = vg2[tid + i * BT]; }
        }

        // ---- QK^T : S = Qh*Kh + Ql*Kh + Qh*Kl  (3-pass fp16 split)
        float S[8][4];
        #pragma unroll
        for (int nt = 0; nt < 8; ++nt)
            #pragma unroll
            for (int j = 0; j < 4; ++j) S[nt][j] = 0.0f;

        #pragma unroll
        for (int nt = 0; nt < 8; ++nt) {
            #pragma unroll
            for (int ks = 0; ks < 4; ++ks) {
                uint32_t a = smb + swz(nt * 8 + lr8, ks * 2 + hi8);
                uint32_t bh0, bh1, bl0, bl1;
                ldsm_x2(bh0, bh1, a + SM_KH);
                ldsm_x2(bl0, bl1, a + SM_KL);
                mma16816(S[nt], qh[ks], bh0, bh1);
                mma16816(S[nt], ql[ks], bh0, bh1);
                mma16816(S[nt], qh[ks], bl0, bl1);
            }
        }

        // ---- online softmax (rows g and g+8; reductions across 4 lanes)
        float mx0 = -1e30f, mx1 = -1e30f;
        #pragma unroll
        for (int nt = 0; nt < 8; ++nt) {
            mx0 = fmaxf(mx0, fmaxf(S[nt][0], S[nt][1]));
            mx1 = fmaxf(mx1, fmaxf(S[nt][2], S[nt][3]));
        }
        mx0 = fmaxf(mx0, __shfl_xor_sync(0xffffffffu, mx0, 1));
        mx0 = fmaxf(mx0, __shfl_xor_sync(0xffffffffu, mx0, 2));
        mx1 = fmaxf(mx1, __shfl_xor_sync(0xffffffffu, mx1, 1));
        mx1 = fmaxf(mx1, __shfl_xor_sync(0xffffffffu, mx1, 2));
        float mn0 = fmaxf(m0, mx0), mn1 = fmaxf(m1, mx1);
        float c0 = __expf(m0 - mn0), c1 = __expf(m1 - mn1);
        float s0 = 0.0f, s1 = 0.0f;
        #pragma unroll
        for (int nt = 0; nt < 8; ++nt) {
            S[nt][0] = __expf(S[nt][0] - mn0);
            S[nt][1] = __expf(S[nt][1] - mn0);
            S[nt][2] = __expf(S[nt][2] - mn1);
            S[nt][3] = __expf(S[nt][3] - mn1);
            s0 += S[nt][0] + S[nt][1];
            s1 += S[nt][2] + S[nt][3];
        }
        s0 += __shfl_xor_sync(0xffffffffu, s0, 1);
        s0 += __shfl_xor_sync(0xffffffffu, s0, 2);
        s1 += __shfl_xor_sync(0xffffffffu, s1, 1);
        s1 += __shfl_xor_sync(0xffffffffu, s1, 2);
        l0 = l0 * c0 + s0;
        l1 = l1 * c1 + s1;
        m0 = mn0; m1 = mn1;
        if (t > 0) {
            #pragma unroll
            for (int nd = 0; nd < 8; ++nd) {
                O[nd][0] *= c0; O[nd][1] *= c0;
                O[nd][2] *= c1; O[nd][3] *= c1;
            }
        }

        // ---- PV : O += P * V   (P c-frag -> a-frag in registers)
        #pragma unroll
        for (int kp = 0; kp < 4; ++kp) {
            uint32_t a[4];
            a[0] = packh2(S[2*kp][1],   S[2*kp][0]);
            a[1] = packh2(S[2*kp][3],   S[2*kp][2]);
            a[2] = packh2(S[2*kp+1][1], S[2*kp+1][0]);
            a[3] = packh2(S[2*kp+1][3], S[2*kp+1][2]);
            #pragma unroll
            for (int nd = 0; nd < 8; ++nd) {
                uint32_t b0, b1;
                ldsm_x2t(b0, b1, smb + SM_V + swz(kp * 16 + (lane & 15), nd));
                mma16816(O[nd], a, b0, b1);
            }
        }
        __syncthreads();
    }

    // ================= epilogue =================
    float inv0 = 1.0f / l0, inv1 = 1.0f / l1;
    float* o0 = Out + hb + (size_t)(qbase + wrow + g) * HD + 2 * tq;
    float* o1 = o0 + 8 * HD;
    #pragma unroll
    for (int nd = 0; nd < 8; ++nd) {
        *(float2*)(o0 + nd * 8) = make_float2(O[nd][0] * inv0, O[nd][1] * inv0);
        *(float2*)(o1 + nd * 8) = make_float2(O[nd][2] * inv1, O[nd][3] * inv1);
    }
}

extern "C" void kernel_launch(void* const* d_in, const int* in_sizes, int n_in,
                              void* d_out, int out_size) {
    const float* Q = (const float*)d_in[0];
    const float* K = (const float*)d_in[1];
    const float* V = (const float*)d_in[2];
    float* O = (float*)d_out;

    dim3 grid(SEQ / BM, 64);
    attn_mma<<<grid, BT>>>(Q, K, V, O);
}

// round 10
// speedup vs baseline: 9.8629x; 1.1272x over previous
#include <cuda_runtime.h>
#include <cuda_fp16.h>
#include <cstdint>

// softmax(Q K^T) V — B=4,H=16,S=2048,D=64 fp32.
// FA2 mma.sync.m16n8k16 fp16, 3-pass hi/lo QK split (fp32-grade scores).
// R7: 2 CTAs/SM (cp.async staging instead of reg prefetch, <=128 regs),
//     ldmatrix.x4 everywhere, log2e folded into K -> ex2.approx.

#define SEQ 2048
#define HD  64
#define BM  128
#define BN  64
#define NT  (SEQ / BN)
#define BT  256
#define L2E 1.4426950408889634f

// dynamic smem layout
#define SM_KH 0         // K hi fp16, 64x64 (8KB)
#define SM_KL 8192      // K lo fp16 (8KB)
#define SM_V  16384     // V fp16 (8KB)
#define SM_SK 24576     // K fp32 staging (16KB)
#define SM_SV 40960     // V fp32 staging (16KB)
#define SMEM_DYN 57344

__device__ __forceinline__ uint32_t swz(uint32_t r, uint32_t c) {
    return r * 128u + ((c ^ (r & 7u)) << 4);
}
__device__ __forceinline__ void ldsm_x4(uint32_t& r0, uint32_t& r1, uint32_t& r2, uint32_t& r3, uint32_t a) {
    asm volatile("ldmatrix.sync.aligned.m8n8.x4.shared.b16 {%0,%1,%2,%3}, [%4];"
                 : "=r"(r0), "=r"(r1), "=r"(r2), "=r"(r3) : "r"(a));
}
__device__ __forceinline__ void ldsm_x4t(uint32_t& r0, uint32_t& r1, uint32_t& r2, uint32_t& r3, uint32_t a) {
    asm volatile("ldmatrix.sync.aligned.m8n8.x4.trans.shared.b16 {%0,%1,%2,%3}, [%4];"
                 : "=r"(r0), "=r"(r1), "=r"(r2), "=r"(r3) : "r"(a));
}
__device__ __forceinline__ void mma16816(float* d, const uint32_t* a, uint32_t b0, uint32_t b1) {
    asm volatile("mma.sync.aligned.m16n8k16.row.col.f32.f16.f16.f32 "
                 "{%0,%1,%2,%3}, {%4,%5,%6,%7}, {%8,%9}, {%0,%1,%2,%3};"
                 : "+f"(d[0]), "+f"(d[1]), "+f"(d[2]), "+f"(d[3])
                 : "r"(a[0]), "r"(a[1]), "r"(a[2]), "r"(a[3]), "r"(b0), "r"(b1));
}
__device__ __forceinline__ uint32_t packh2(float hi, float lo) {
    uint32_t d;
    asm("cvt.rn.f16x2.f32 %0, %1, %2;" : "=r"(d) : "f"(hi), "f"(lo));
    return d;
}
__device__ __forceinline__ float ex2(float x) {
    float y; asm("ex2.approx.ftz.f32 %0, %1;" : "=f"(y) : "f"(x)); return y;
}
__device__ __forceinline__ void cpa16(uint32_t s, const void* g) {
    asm volatile("cp.async.cg.shared.global [%0], [%1], 16;" :: "r"(s), "l"(g));
}
__device__ __forceinline__ void cpcommit() { asm volatile("cp.async.commit_group;"); }
__device__ __forceinline__ void cpwait0()  { asm volatile("cp.async.wait_group 0;"); }

__global__ __launch_bounds__(BT, 2)
void attn_mma2(const float* __restrict__ Q, const float* __restrict__ K,
               const float* __restrict__ V, float* __restrict__ Out) {
    extern __shared__ __align__(1024) char dsm[];
    const uint32_t smb = (uint32_t)__cvta_generic_to_shared(dsm);

    const int tid  = threadIdx.x;
    const int lane = tid & 31;
    const int wid  = tid >> 5;
    const int lr8  = lane & 7;
    const int g    = lane >> 2;
    const int tq   = lane & 3;
    const size_t hb = (size_t)blockIdx.y * SEQ * HD;
    const int qbase = blockIdx.x * BM;
    const int wrow  = wid * 16;

    // ---- kick off cp.async of tile 0 (fp32 staging) ----
    {
        const float* kg = K + hb;
        const float* vg = V + hb;
        #pragma unroll
        for (int i = 0; i < 4; ++i) {
            int idx = tid + i * BT;
            cpa16(smb + SM_SK + idx * 16, kg + idx * 4);
            cpa16(smb + SM_SV + idx * 16, vg + idx * 4);
        }
        cpcommit();
    }

    // ---- Q fragments (hi/lo) via fp16 smem staging at offset 0 ----
    uint32_t qh[4][4], ql[4][4];
    {
        float qv[32];
        const float4* qg = (const float4*)(Q + hb + (size_t)qbase * HD);
        #pragma unroll
        for (int i = 0; i < 8; ++i) {
            float4 f = qg[tid + i * BT];
            qv[i*4+0] = f.x; qv[i*4+1] = f.y; qv[i*4+2] = f.z; qv[i*4+3] = f.w;
        }
        #pragma unroll
        for (int i = 0; i < 8; ++i) {
            int idx = tid + i * BT;
            int r = idx >> 4, c4 = idx & 15;
            uint32_t off = swz(r, c4 >> 1) + (c4 & 1) * 8;
            *(__half2*)(dsm + off)     = __halves2half2(__float2half_rn(qv[i*4+0]), __float2half_rn(qv[i*4+1]));
            *(__half2*)(dsm + off + 4) = __halves2half2(__float2half_rn(qv[i*4+2]), __float2half_rn(qv[i*4+3]));
        }
        __syncthreads();
        #pragma unroll
        for (int ks = 0; ks < 4; ++ks) {
            int qd = lane >> 3;
            int r = wrow + ((qd & 1) << 3) + lr8;
            int c = ks * 2 + (qd >> 1);
            ldsm_x4(qh[ks][0], qh[ks][1], qh[ks][2], qh[ks][3], smb + swz(r, c));
        }
        __syncthreads();
        #pragma unroll
        for (int i = 0; i < 8; ++i) {
            int idx = tid + i * BT;
            int r = idx >> 4, c4 = idx & 15;
            uint32_t off = swz(r, c4 >> 1) + (c4 & 1) * 8;
            float r0 = qv[i*4+0] - __half2float(__float2half_rn(qv[i*4+0]));
            float r1 = qv[i*4+1] - __half2float(__float2half_rn(qv[i*4+1]));
            float r2 = qv[i*4+2] - __half2float(__float2half_rn(qv[i*4+2]));
            float r3 = qv[i*4+3] - __half2float(__float2half_rn(qv[i*4+3]));
            *(__half2*)(dsm + off)     = __halves2half2(__float2half_rn(r0), __float2half_rn(r1));
            *(__half2*)(dsm + off + 4) = __halves2half2(__float2half_rn(r2), __float2half_rn(r3));
        }
        __syncthreads();
        #pragma unroll
        for (int ks = 0; ks < 4; ++ks) {
            int qd = lane >> 3;
            int r = wrow + ((qd & 1) << 3) + lr8;
            int c = ks * 2 + (qd >> 1);
            ldsm_x4(ql[ks][0], ql[ks][1], ql[ks][2], ql[ks][3], smb + swz(r, c));
        }
    }
    cpwait0();
    __syncthreads();   // staging tile 0 ready; Q staging region dead

    float O[8][4];
    #pragma unroll
    for (int nd = 0; nd < 8; ++nd)
        #pragma unroll
        for (int j = 0; j < 4; ++j) O[nd][j] = 0.0f;
    float m0 = -1e30f, m1 = -1e30f, l0 = 0.0f, l1 = 0.0f;

    for (int t = 0; t < NT; ++t) {
        // ---- convert fp32 staging -> fp16 tiles (K scaled by log2e, hi/lo split)
        #pragma unroll
        for (int i = 0; i < 4; ++i) {
            int idx = tid + i * BT;
            int r = idx >> 4, c4 = idx & 15;
            uint32_t off = swz(r, c4 >> 1) + (c4 & 1) * 8;
            float4 f = ((const float4*)(dsm + SM_SK))[idx];
            float x0 = f.x * L2E, x1 = f.y * L2E, x2 = f.z * L2E, x3 = f.w * L2E;
            __half h0 = __float2half_rn(x0), h1 = __float2half_rn(x1);
            __half h2 = __float2half_rn(x2), h3 = __float2half_rn(x3);
            *(__half2*)(dsm + SM_KH + off)     = __halves2half2(h0, h1);
            *(__half2*)(dsm + SM_KH + off + 4) = __halves2half2(h2, h3);
            *(__half2*)(dsm + SM_KL + off)     = __halves2half2(
                __float2half_rn(x0 - __half2float(h0)), __float2half_rn(x1 - __half2float(h1)));
            *(__half2*)(dsm + SM_KL + off + 4) = __halves2half2(
                __float2half_rn(x2 - __half2float(h2)), __float2half_rn(x3 - __half2float(h3)));
            float4 v = ((const float4*)(dsm + SM_SV))[idx];
            *(__half2*)(dsm + SM_V + off)      = __halves2half2(__float2half_rn(v.x), __float2half_rn(v.y));
            *(__half2*)(dsm + SM_V + off + 4)  = __halves2half2(__float2half_rn(v.z), __float2half_rn(v.w));
        }
        __syncthreads();

        // ---- start async load of tile t+1 into staging
        if (t + 1 < NT) {
            const float* kg = K + hb + (size_t)(t + 1) * BN * HD;
            const float* vg = V + hb + (size_t)(t + 1) * BN * HD;
            #pragma unroll
            for (int i = 0; i < 4; ++i) {
                int idx = tid + i * BT;
                cpa16(smb + SM_SK + idx * 16, kg + idx * 4);
                cpa16(smb + SM_SV + idx * 16, vg + idx * 4);
            }
            cpcommit();
        }

        // ---- QK^T: 3-pass fp16 split, ldmatrix.x4 B-frags
        float S[8][4];
        #pragma unroll
        for (int nt = 0; nt < 8; ++nt)
            #pragma unroll
            for (int j = 0; j < 4; ++j) S[nt][j] = 0.0f;

        #pragma unroll
        for (int ntp = 0; ntp < 4; ++ntp) {
            #pragma unroll
            for (int ks = 0; ks < 4; ++ks) {
                int r = ntp * 16 + ((lane >> 4) << 3) + lr8;
                int c = ks * 2 + ((lane >> 3) & 1);
                uint32_t a = smb + swz(r, c);
                uint32_t bh0, bh1, bh2, bh3, bl0, bl1, bl2, bl3;
                ldsm_x4(bh0, bh1, bh2, bh3, a + SM_KH);
                ldsm_x4(bl0, bl1, bl2, bl3, a + SM_KL);
                mma16816(S[2*ntp],   qh[ks], bh0, bh1);
                mma16816(S[2*ntp],   ql[ks], bh0, bh1);
                mma16816(S[2*ntp],   qh[ks], bl0, bl1);
                mma16816(S[2*ntp+1], qh[ks], bh2, bh3);
                mma16816(S[2*ntp+1], ql[ks], bh2, bh3);
                mma16816(S[2*ntp+1], qh[ks], bl2, bl3);
            }
        }

        // ---- online softmax (base-2 domain; log2e pre-folded into K)
        float mx0 = -1e30f, mx1 = -1e30f;
        #pragma unroll
        for (int nt = 0; nt < 8; ++nt) {
            mx0 = fmaxf(mx0, fmaxf(S[nt][0], S[nt][1]));
            mx1 = fmaxf(mx1, fmaxf(S[nt][2], S[nt][3]));
        }
        mx0 = fmaxf(mx0, __shfl_xor_sync(0xffffffffu, mx0, 1));
        mx0 = fmaxf(mx0, __shfl_xor_sync(0xffffffffu, mx0, 2));
        mx1 = fmaxf(mx1, __shfl_xor_sync(0xffffffffu, mx1, 1));
        mx1 = fmaxf(mx1, __shfl_xor_sync(0xffffffffu, mx1, 2));
        float mn0 = fmaxf(m0, mx0), mn1 = fmaxf(m1, mx1);
        float c0 = ex2(m0 - mn0), c1 = ex2(m1 - mn1);
        float s0 = 0.0f, s1 = 0.0f;
        #pragma unroll
        for (int nt = 0; nt < 8; ++nt) {
            S[nt][0] = ex2(S[nt][0] - mn0);
            S[nt][1] = ex2(S[nt][1] - mn0);
            S[nt][2] = ex2(S[nt][2] - mn1);
            S[nt][3] = ex2(S[nt][3] - mn1);
            s0 += S[nt][0] + S[nt][1];
            s1 += S[nt][2] + S[nt][3];
        }
        s0 += __shfl_xor_sync(0xffffffffu, s0, 1);
        s0 += __shfl_xor_sync(0xffffffffu, s0, 2);
        s1 += __shfl_xor_sync(0xffffffffu, s1, 1);
        s1 += __shfl_xor_sync(0xffffffffu, s1, 2);
        l0 = l0 * c0 + s0;
        l1 = l1 * c1 + s1;
        m0 = mn0; m1 = mn1;
        if (t > 0) {
            #pragma unroll
            for (int nd = 0; nd < 8; ++nd) {
                O[nd][0] *= c0; O[nd][1] *= c0;
                O[nd][2] *= c1; O[nd][3] *= c1;
            }
        }

        // ---- PV: P c-frag -> a-frag, ldmatrix.x4.trans V
        #pragma unroll
        for (int kp = 0; kp < 4; ++kp) {
            uint32_t a[4];
            a[0] = packh2(S[2*kp][1],   S[2*kp][0]);
            a[1] = packh2(S[2*kp][3],   S[2*kp][2]);
            a[2] = packh2(S[2*kp+1][1], S[2*kp+1][0]);
            a[3] = packh2(S[2*kp+1][3], S[2*kp+1][2]);
            #pragma unroll
            for (int ndp = 0; ndp < 4; ++ndp) {
                int r = kp * 16 + (lane & 15);
                int c = ndp * 2 + (lane >> 4);
                uint32_t v0, v1, v2, v3;
                ldsm_x4t(v0, v1, v2, v3, smb + SM_V + swz(r, c));
                mma16816(O[2*ndp],   a, v0, v1);
                mma16816(O[2*ndp+1], a, v2, v3);
            }
        }
        cpwait0();
        __syncthreads();
    }

    // ---- epilogue
    float inv0 = 1.0f / l0, inv1 = 1.0f / l1;
    float* o0 = Out + hb + (size_t)(qbase + wrow + g) * HD + 2 * tq;
    float* o1 = o0 + 8 * HD;
    #pragma unroll
    for (int nd = 0; nd < 8; ++nd) {
        *(float2*)(o0 + nd * 8) = make_float2(O[nd][0] * inv0, O[nd][1] * inv0);
        *(float2*)(o1 + nd * 8) = make_float2(O[nd][2] * inv1, O[nd][3] * inv1);
    }
}

extern "C" void kernel_launch(void* const* d_in, const int* in_sizes, int n_in,
                              void* d_out, int out_size) {
    const float* Q = (const float*)d_in[0];
    const float* K = (const float*)d_in[1];
    const float* V = (const float*)d_in[2];
    float* O = (float*)d_out;

    cudaFuncSetAttribute(attn_mma2, cudaFuncAttributeMaxDynamicSharedMemorySize, SMEM_DYN);
    dim3 grid(SEQ / BM, 64);
    attn_mma2<<<grid, BT, SMEM_DYN>>>(Q, K, V, O);
}

// round 11
// speedup vs baseline: 10.6979x; 1.0847x over previous
#include <cuda_runtime.h>
#include <cuda_fp16.h>
#include <cstdint>

// softmax(Q K^T) V — B=4,H=16,S=2048,D=64 fp32.
// R11: two kernels. prep_kv converts K->fp16 hi/lo (log2e folded) and V->fp16
// ONCE per head, writing tiles in the final swizzled smem layout to __device__
// scratch. attn kernel then cp.asyncs ldmatrix-ready 24KB tiles (double
// buffered) -- no per-tile conversion, no fp32 staging.

#define SEQ 2048
#define HD  64
#define BM  128
#define BN  64
#define NT  (SEQ / BN)
#define BT  256
#define L2E 1.4426950408889634f

#define TILE_B   8192          // one region (64x64 fp16, swizzled)
#define TILE3_B  (3 * TILE_B)  // KH + KL + V
#define SMEM_DYN (2 * TILE3_B) // double buffer, 48KB

// scratch: [head][tile][region][8192B] = 64*32*3*8192 = 48MB
__device__ __align__(16) unsigned char g_kv[64 * 32 * 3 * 8192];

__device__ __forceinline__ uint32_t swz(uint32_t r, uint32_t c) {
    return r * 128u + ((c ^ (r & 7u)) << 4);
}
__device__ __forceinline__ void ldsm_x4(uint32_t& r0, uint32_t& r1, uint32_t& r2, uint32_t& r3, uint32_t a) {
    asm volatile("ldmatrix.sync.aligned.m8n8.x4.shared.b16 {%0,%1,%2,%3}, [%4];"
                 : "=r"(r0), "=r"(r1), "=r"(r2), "=r"(r3) : "r"(a));
}
__device__ __forceinline__ void ldsm_x4t(uint32_t& r0, uint32_t& r1, uint32_t& r2, uint32_t& r3, uint32_t a) {
    asm volatile("ldmatrix.sync.aligned.m8n8.x4.trans.shared.b16 {%0,%1,%2,%3}, [%4];"
                 : "=r"(r0), "=r"(r1), "=r"(r2), "=r"(r3) : "r"(a));
}
__device__ __forceinline__ void mma16816(float* d, const uint32_t* a, uint32_t b0, uint32_t b1) {
    asm volatile("mma.sync.aligned.m16n8k16.row.col.f32.f16.f16.f32 "
                 "{%0,%1,%2,%3}, {%4,%5,%6,%7}, {%8,%9}, {%0,%1,%2,%3};"
                 : "+f"(d[0]), "+f"(d[1]), "+f"(d[2]), "+f"(d[3])
                 : "r"(a[0]), "r"(a[1]), "r"(a[2]), "r"(a[3]), "r"(b0), "r"(b1));
}
__device__ __forceinline__ uint32_t packh2(float hi, float lo) {
    uint32_t d;
    asm("cvt.rn.f16x2.f32 %0, %1, %2;" : "=r"(d) : "f"(hi), "f"(lo));
    return d;
}
__device__ __forceinline__ float ex2(float x) {
    float y; asm("ex2.approx.ftz.f32 %0, %1;" : "=f"(y) : "f"(x)); return y;
}
__device__ __forceinline__ void cpa16(uint32_t s, const void* g) {
    asm volatile("cp.async.cg.shared.global [%0], [%1], 16;" :: "r"(s), "l"(g));
}
__device__ __forceinline__ void cpcommit() { asm volatile("cp.async.commit_group;"); }
__device__ __forceinline__ void cpwait0()  { asm volatile("cp.async.wait_group 0;"); }

// ======================= pre-pass: K/V -> swizzled fp16 tiles ==============
__global__ __launch_bounds__(256, 4)
void prep_kv(const float* __restrict__ K, const float* __restrict__ V) {
    const int tile = blockIdx.x;          // 0..31
    const int head = blockIdx.y;          // 0..63
    const int tid  = threadIdx.x;
    const float* kg = K + ((size_t)head * SEQ + (size_t)tile * BN) * HD;
    const float* vg = V + ((size_t)head * SEQ + (size_t)tile * BN) * HD;
    unsigned char* base = g_kv + (size_t)(head * NT + tile) * TILE3_B;

    #pragma unroll
    for (int i = 0; i < 4; ++i) {
        int idx = tid + i * 256;              // quad id 0..1023
        int r  = idx >> 4;                    // key row 0..63
        int c4 = idx & 15;                    // quad col 0..15
        uint32_t off = swz(r, c4 >> 1) + (c4 & 1) * 8;

        float4 f = *(const float4*)(kg + r * HD + c4 * 4);
        float x0 = f.x * L2E, x1 = f.y * L2E, x2 = f.z * L2E, x3 = f.w * L2E;
        __half h0 = __float2half_rn(x0), h1 = __float2half_rn(x1);
        __half h2 = __float2half_rn(x2), h3 = __float2half_rn(x3);
        *(__half2*)(base + off)     = __halves2half2(h0, h1);
        *(__half2*)(base + off + 4) = __halves2half2(h2, h3);
        *(__half2*)(base + TILE_B + off)     = __halves2half2(
            __float2half_rn(x0 - __half2float(h0)), __float2half_rn(x1 - __half2float(h1)));
        *(__half2*)(base + TILE_B + off + 4) = __halves2half2(
            __float2half_rn(x2 - __half2float(h2)), __float2half_rn(x3 - __half2float(h3)));

        float4 v = *(const float4*)(vg + r * HD + c4 * 4);
        *(__half2*)(base + 2 * TILE_B + off)     = __halves2half2(__float2half_rn(v.x), __float2half_rn(v.y));
        *(__half2*)(base + 2 * TILE_B + off + 4) = __halves2half2(__float2half_rn(v.z), __float2half_rn(v.w));
    }
}

// ======================= main attention kernel =============================
__global__ __launch_bounds__(BT, 2)
void attn_mma3(const float* __restrict__ Q, float* __restrict__ Out) {
    extern __shared__ __align__(1024) char dsm[];
    const uint32_t smb = (uint32_t)__cvta_generic_to_shared(dsm);

    const int tid  = threadIdx.x;
    const int lane = tid & 31;
    const int wid  = tid >> 5;
    const int lr8  = lane & 7;
    const int g    = lane >> 2;
    const int tq   = lane & 3;
    const int head = blockIdx.y;
    const size_t hb = (size_t)head * SEQ * HD;
    const int qbase = blockIdx.x * BM;
    const int wrow  = wid * 16;
    const unsigned char* gkv = g_kv + (size_t)head * NT * TILE3_B;

    // ---- prefetch tile 0 -> buf0 (pure linear copy; layout pre-baked)
    #pragma unroll
    for (int i = 0; i < 6; ++i) {
        int idx = tid + i * BT;               // 16B chunk 0..1535
        cpa16(smb + idx * 16, gkv + idx * 16);
    }
    cpcommit();

    // ---- Q fragments (hi/lo) staged in buf1 (not written until prefetch(1))
    uint32_t qh[4][4], ql[4][4];
    {
        char* qs = dsm + TILE3_B;
        const uint32_t qsb = smb + TILE3_B;
        float qv[32];
        const float4* qg = (const float4*)(Q + hb + (size_t)qbase * HD);
        #pragma unroll
        for (int i = 0; i < 8; ++i) {
            float4 f = qg[tid + i * BT];
            qv[i*4+0] = f.x; qv[i*4+1] = f.y; qv[i*4+2] = f.z; qv[i*4+3] = f.w;
        }
        #pragma unroll
        for (int i = 0; i < 8; ++i) {
            int idx = tid + i * BT;
            int r = idx >> 4, c4 = idx & 15;
            uint32_t off = swz(r, c4 >> 1) + (c4 & 1) * 8;
            *(__half2*)(qs + off)     = __halves2half2(__float2half_rn(qv[i*4+0]), __float2half_rn(qv[i*4+1]));
            *(__half2*)(qs + off + 4) = __halves2half2(__float2half_rn(qv[i*4+2]), __float2half_rn(qv[i*4+3]));
        }
        __syncthreads();
        #pragma unroll
        for (int ks = 0; ks < 4; ++ks) {
            int qd = lane >> 3;
            int r = wrow + ((qd & 1) << 3) + lr8;
            int c = ks * 2 + (qd >> 1);
            ldsm_x4(qh[ks][0], qh[ks][1], qh[ks][2], qh[ks][3], qsb + swz(r, c));
        }
        __syncthreads();
        #pragma unroll
        for (int i = 0; i < 8; ++i) {
            int idx = tid + i * BT;
            int r = idx >> 4, c4 = idx & 15;
            uint32_t off = swz(r, c4 >> 1) + (c4 & 1) * 8;
            float r0 = qv[i*4+0] - __half2float(__float2half_rn(qv[i*4+0]));
            float r1 = qv[i*4+1] - __half2float(__float2half_rn(qv[i*4+1]));
            float r2 = qv[i*4+2] - __half2float(__float2half_rn(qv[i*4+2]));
            float r3 = qv[i*4+3] - __half2float(__float2half_rn(qv[i*4+3]));
            *(__half2*)(qs + off)     = __halves2half2(__float2half_rn(r0), __float2half_rn(r1));
            *(__half2*)(qs + off + 4) = __halves2half2(__float2half_rn(r2), __float2half_rn(r3));
        }
        __syncthreads();
        #pragma unroll
        for (int ks = 0; ks < 4; ++ks) {
            int qd = lane >> 3;
            int r = wrow + ((qd & 1) << 3) + lr8;
            int c = ks * 2 + (qd >> 1);
            ldsm_x4(ql[ks][0], ql[ks][1], ql[ks][2], ql[ks][3], qsb + swz(r, c));
        }
    }

    float O[8][4];
    #pragma unroll
    for (int nd = 0; nd < 8; ++nd)
        #pragma unroll
        for (int j = 0; j < 4; ++j) O[nd][j] = 0.0f;
    float m0 = -1e30f, m1 = -1e30f, l0 = 0.0f, l1 = 0.0f;

    for (int t = 0; t < NT; ++t) {
        cpwait0();
        __syncthreads();   // tile t landed; all compute on buf[(t+1)&1] done

        if (t + 1 < NT) {
            const unsigned char* gt = gkv + (size_t)(t + 1) * TILE3_B;
            const uint32_t dst = smb + ((t + 1) & 1) * TILE3_B;
            #pragma unroll
            for (int i = 0; i < 6; ++i) {
                int idx = tid + i * BT;
                cpa16(dst + idx * 16, gt + idx * 16);
            }
            cpcommit();
        }

        const uint32_t B = smb + (t & 1) * TILE3_B;   // KH at +0, KL at +8192, V at +16384

        // ---- QK^T: 3-pass fp16 split
        float S[8][4];
        #pragma unroll
        for (int nt = 0; nt < 8; ++nt)
            #pragma unroll
            for (int j = 0; j < 4; ++j) S[nt][j] = 0.0f;

        #pragma unroll
        for (int ntp = 0; ntp < 4; ++ntp) {
            #pragma unroll
            for (int ks = 0; ks < 4; ++ks) {
                int r = ntp * 16 + ((lane >> 4) << 3) + lr8;
                int c = ks * 2 + ((lane >> 3) & 1);
                uint32_t a = B + swz(r, c);
                uint32_t bh0, bh1, bh2, bh3, bl0, bl1, bl2, bl3;
                ldsm_x4(bh0, bh1, bh2, bh3, a);
                ldsm_x4(bl0, bl1, bl2, bl3, a + TILE_B);
                mma16816(S[2*ntp],   qh[ks], bh0, bh1);
                mma16816(S[2*ntp],   ql[ks], bh0, bh1);
                mma16816(S[2*ntp],   qh[ks], bl0, bl1);
                mma16816(S[2*ntp+1], qh[ks], bh2, bh3);
                mma16816(S[2*ntp+1], ql[ks], bh2, bh3);
                mma16816(S[2*ntp+1], qh[ks], bl2, bl3);
            }
        }

        // ---- online softmax (base-2 domain)
        float mx0 = -1e30f, mx1 = -1e30f;
        #pragma unroll
        for (int nt = 0; nt < 8; ++nt) {
            mx0 = fmaxf(mx0, fmaxf(S[nt][0], S[nt][1]));
            mx1 = fmaxf(mx1, fmaxf(S[nt][2], S[nt][3]));
        }
        mx0 = fmaxf(mx0, __shfl_xor_sync(0xffffffffu, mx0, 1));
        mx0 = fmaxf(mx0, __shfl_xor_sync(0xffffffffu, mx0, 2));
        mx1 = fmaxf(mx1, __shfl_xor_sync(0xffffffffu, mx1, 1));
        mx1 = fmaxf(mx1, __shfl_xor_sync(0xffffffffu, mx1, 2));
        float mn0 = fmaxf(m0, mx0), mn1 = fmaxf(m1, mx1);
        float c0 = ex2(m0 - mn0), c1 = ex2(m1 - mn1);
        float s0 = 0.0f, s1 = 0.0f;
        #pragma unroll
        for (int nt = 0; nt < 8; ++nt) {
            S[nt][0] = ex2(S[nt][0] - mn0);
            S[nt][1] = ex2(S[nt][1] - mn0);
            S[nt][2] = ex2(S[nt][2] - mn1);
            S[nt][3] = ex2(S[nt][3] - mn1);
            s0 += S[nt][0] + S[nt][1];
            s1 += S[nt][2] + S[nt][3];
        }
        s0 += __shfl_xor_sync(0xffffffffu, s0, 1);
        s0 += __shfl_xor_sync(0xffffffffu, s0, 2);
        s1 += __shfl_xor_sync(0xffffffffu, s1, 1);
        s1 += __shfl_xor_sync(0xffffffffu, s1, 2);
        l0 = l0 * c0 + s0;
        l1 = l1 * c1 + s1;
        m0 = mn0; m1 = mn1;
        if (t > 0) {
            #pragma unroll
            for (int nd = 0; nd < 8; ++nd) {
                O[nd][0] *= c0; O[nd][1] *= c0;
                O[nd][2] *= c1; O[nd][3] *= c1;
            }
        }

        // ---- PV
        #pragma unroll
        for (int kp = 0; kp < 4; ++kp) {
            uint32_t a[4];
            a[0] = packh2(S[2*kp][1],   S[2*kp][0]);
            a[1] = packh2(S[2*kp][3],   S[2*kp][2]);
            a[2] = packh2(S[2*kp+1][1], S[2*kp+1][0]);
            a[3] = packh2(S[2*kp+1][3], S[2*kp+1][2]);
            #pragma unroll
            for (int ndp = 0; ndp < 4; ++ndp) {
                int r = kp * 16 + (lane & 15);
                int c = ndp * 2 + (lane >> 4);
                uint32_t v0, v1, v2, v3;
                ldsm_x4t(v0, v1, v2, v3, B + 2 * TILE_B + swz(r, c));
                mma16816(O[2*ndp],   a, v0, v1);
                mma16816(O[2*ndp+1], a, v2, v3);
            }
        }
    }

    // ---- epilogue
    float inv0 = 1.0f / l0, inv1 = 1.0f / l1;
    float* o0 = Out + hb + (size_t)(qbase + wrow + g) * HD + 2 * tq;
    float* o1 = o0 + 8 * HD;
    #pragma unroll
    for (int nd = 0; nd < 8; ++nd) {
        *(float2*)(o0 + nd * 8) = make_float2(O[nd][0] * inv0, O[nd][1] * inv0);
        *(float2*)(o1 + nd * 8) = make_float2(O[nd][2] * inv1, O[nd][3] * inv1);
    }
}

extern "C" void kernel_launch(void* const* d_in, const int* in_sizes, int n_in,
                              void* d_out, int out_size) {
    const float* Q = (const float*)d_in[0];
    const float* K = (const float*)d_in[1];
    const float* V = (const float*)d_in[2];
    float* O = (float*)d_out;

    prep_kv<<<dim3(NT, 64), 256>>>(K, V);

    cudaFuncSetAttribute(attn_mma3, cudaFuncAttributeMaxDynamicSharedMemorySize, SMEM_DYN);
    dim3 grid(SEQ / BM, 64);
    attn_mma3<<<grid, BT, SMEM_DYN>>>(Q, O);
}